// round 9
// baseline (speedup 1.0000x reference)
#include <cuda_runtime.h>
#include <cuda_fp16.h>
#include <math.h>
#include <stdint.h>

// ---------------------------------------------------------------------------
// Problem constants: B=4, L=1024, DH=2048, D=128, HQ=16, HK=HV=4, H=16, K=4
// Fused projection layout (columns of xcat / rows of wcat):
//   [0,2048) q | [2048,2560) k | [2560,3072) v | [3072,5120) g
// ---------------------------------------------------------------------------
#define ROWS 4096
#define DH_  2048
#define DHEAD 128
#define NH   16
#define NHK  4
#define SEQ  1024
#define NCAT 5120
#define COL_K 2048
#define COL_V 2560
#define COL_G 3072

// ---------------- device scratch (allocation-free rule) --------------------
__device__ float g_xcat[ROWS * NCAT];
__device__ float g_q [ROWS * DH_];
__device__ float g_k [ROWS * 512];
__device__ float g_v [ROWS * 512];
__device__ float g_beta[ROWS * NH];
__device__ float g_gd  [ROWS * NH];
__device__ float g_o [ROWS * DH_];

__device__ __align__(256) __half g_xhi[ROWS * DH_];
__device__ __align__(256) __half g_of [ROWS * DH_];
__device__ __align__(256) __half g_wcat[NCAT * DH_];     // [N=5120, K=2048] fp16
__device__ __align__(256) __half g_wot[DH_ * DH_];       // Wo^T fp16

// ---------------------------------------------------------------------------
// PTX helpers (baseline ISA only)
// ---------------------------------------------------------------------------
__device__ __forceinline__ uint32_t smem_to_u32(const void* p) {
    uint32_t a;
    asm("{ .reg .u64 t; cvta.to.shared.u64 t, %1; cvt.u32.u64 %0, t; }"
        : "=r"(a) : "l"(p));
    return a;
}
__device__ __forceinline__ void cp16(uint32_t s, const void* g) {
    asm volatile("cp.async.cg.shared.global [%0], [%1], 16;"
                 :: "r"(s), "l"(g) : "memory");
}
#define CP_COMMIT() asm volatile("cp.async.commit_group;" ::: "memory")

#define LDSM4(d, addr) \
    asm volatile("ldmatrix.sync.aligned.m8n8.x4.shared.b16 {%0,%1,%2,%3}, [%4];" \
        : "=r"((d)[0]), "=r"((d)[1]), "=r"((d)[2]), "=r"((d)[3]) : "r"(addr))

#define MMA16816F(c, a, b) \
    asm volatile("mma.sync.aligned.m16n8k16.row.col.f32.f16.f16.f32 " \
        "{%0,%1,%2,%3}, {%4,%5,%6,%7}, {%8,%9}, {%0,%1,%2,%3};" \
        : "+f"((c)[0]), "+f"((c)[1]), "+f"((c)[2]), "+f"((c)[3]) \
        : "r"((a)[0]), "r"((a)[1]), "r"((a)[2]), "r"((a)[3]), \
          "r"((b)[0]), "r"((b)[1]))

// ---------------------------------------------------------------------------
// fused_prep: block-range routed — tof16 | weight transposes | betag
//   blocks [0,16384): x -> fp16
//   blocks [16384,30720): transposes Wq|Wk|Wv|Wg -> wcat, Wo -> wot
//   blocks [30720,31232): exact fp32 beta/g thin-GEMM (8 rows per block)
// ---------------------------------------------------------------------------
#define PREP_T0 16384
#define PREP_T1 30720
#define PREP_NB 31232

__global__ __launch_bounds__(256) void fused_prep(
    const float* __restrict__ x,
    const float* __restrict__ Wq, const float* __restrict__ Wk,
    const float* __restrict__ Wv, const float* __restrict__ Wg,
    const float* __restrict__ Wo,
    const float* __restrict__ Wb, const float* __restrict__ Wgk,
    const float* __restrict__ A_log, const float* __restrict__ dt_bias,
    __half* __restrict__ xhi, __half* __restrict__ wcat, __half* __restrict__ wot)
{
    extern __shared__ float sm[];
    const int blk = blockIdx.x;
    const int tid = threadIdx.x;

    if (blk < PREP_T0) {
        // ---- tof16: 256 float2 per block ----
        int i = blk * 256 + tid;
        float2 v = ((const float2*)x)[i];
        ((__half2*)xhi)[i] = __halves2half2(__float2half_rn(v.x), __float2half_rn(v.y));
    } else if (blk < PREP_T1) {
        // ---- transpose W[K,N] -> T[N,K] fp16, 32x32 tiles ----
        float (*t)[33] = (float(*)[33])sm;
        const int idx = blk - PREP_T0;
        const float* W; __half* T; int N, bx, by;
        if (idx < 4096)        { W = Wq; T = wcat;                        N = 2048; int l = idx;         bx = l & 63; by = l >> 6; }
        else if (idx < 5120)   { W = Wk; T = wcat + (size_t)COL_K * DH_;  N =  512; int l = idx - 4096;  bx = l & 15; by = l >> 4; }
        else if (idx < 6144)   { W = Wv; T = wcat + (size_t)COL_V * DH_;  N =  512; int l = idx - 5120;  bx = l & 15; by = l >> 4; }
        else if (idx < 10240)  { W = Wg; T = wcat + (size_t)COL_G * DH_;  N = 2048; int l = idx - 6144;  bx = l & 63; by = l >> 6; }
        else                   { W = Wo; T = wot;                         N = 2048; int l = idx - 10240; bx = l & 63; by = l >> 6; }
        bx <<= 5; by <<= 5;
        const int tx = tid & 31, ty = tid >> 5;
        #pragma unroll
        for (int i = 0; i < 32; i += 8)
            t[ty + i][tx] = W[(size_t)(by + ty + i) * N + bx + tx];
        __syncthreads();
        #pragma unroll
        for (int i = 0; i < 32; i += 8)
            T[(size_t)(bx + ty + i) * DH_ + by + tx] = __float2half_rn(t[tx][ty + i]);
    } else {
        // ---- betag: 8 rows staged in smem (64KB) ----
        const int row0 = (blk - PREP_T1) * 8;
        const float4* xin = (const float4*)(x + (size_t)row0 * DH_);
        float4* xs4 = (float4*)sm;
        for (int i = tid; i < 8 * DH_ / 4; i += 256) xs4[i] = xin[i];
        __syncthreads();

        const int ty   = tid >> 5;
        const int lane = tid & 31;
        const int col  = lane & 15;
        const float* W = (lane < 16) ? Wb : Wgk;
        const float* xr = sm + ty * DH_;

        float s0 = 0.f, s1 = 0.f, s2 = 0.f, s3 = 0.f;
        for (int k = 0; k < DH_; k += 4) {
            s0 = fmaf(xr[k + 0], W[(k + 0) * NH + col], s0);
            s1 = fmaf(xr[k + 1], W[(k + 1) * NH + col], s1);
            s2 = fmaf(xr[k + 2], W[(k + 2) * NH + col], s2);
            s3 = fmaf(xr[k + 3], W[(k + 3) * NH + col], s3);
        }
        float s = (s0 + s1) + (s2 + s3);
        const int row = row0 + ty;
        if (lane < 16) {
            g_beta[row * NH + col] = 1.f / (1.f + expf(-s));
        } else {
            float xg = s + dt_bias[col];
            float sp = (xg > 15.f) ? xg : log1pf(expf(xg));
            g_gd[row * NH + col] = -expf(A_log[col]) * sp;
        }
    }
}

// ---------------------------------------------------------------------------
// 1-pass fp16 GEMM: C[M,N] = A[M,K] @ B[N,K]^T, fp32 accumulate.
// BM=BN=128, BK=64 (128B rows), 3 stages of 32KB (96KB), 256 thr, 2 CTAs/SM.
// ---------------------------------------------------------------------------
#define ST1 32768
#define SM1 (3 * ST1)

__global__ __launch_bounds__(256, 2) void gemm1(
    const __half* __restrict__ A, const __half* __restrict__ B,
    float* __restrict__ C, int N, int K)
{
    extern __shared__ char smem[];
    const uint32_t sb = smem_to_u32(smem);
    const int tid  = threadIdx.x;
    const int lane = tid & 31;
    const int wid  = tid >> 5;
    const int wm   = wid & 1;
    const int wn   = wid >> 1;
    const int brow = blockIdx.y * 128;
    const int bcol = blockIdx.x * 128;
    const size_t K2 = (size_t)K * 2;

    uint32_t swo[4];
    size_t   ga[4], gb[4];
    #pragma unroll
    for (int i = 0; i < 4; i++) {
        int c  = tid + (i << 8);
        int r  = c >> 3, ch = c & 7;
        swo[i] = (uint32_t)(r * 128 + ((ch ^ (r & 7)) << 4));
        ga[i]  = (size_t)(brow + r) * K2 + (size_t)(ch << 4);
        gb[i]  = (size_t)(bcol + r) * K2 + (size_t)(ch << 4);
    }

    const int NK = K >> 6;
    #pragma unroll
    for (int pf = 0; pf < 2; pf++) {
        uint32_t s0 = sb + pf * ST1;
        size_t ko = (size_t)pf << 7;
        #pragma unroll
        for (int i = 0; i < 4; i++) {
            cp16(s0 +     0 + swo[i], (const char*)A + ga[i] + ko);
            cp16(s0 + 16384 + swo[i], (const char*)B + gb[i] + ko);
        }
        CP_COMMIT();
    }

    float acc[4][4][4];
    #pragma unroll
    for (int mi = 0; mi < 4; mi++)
        #pragma unroll
        for (int ni = 0; ni < 4; ni++)
            #pragma unroll
            for (int j = 0; j < 4; j++) acc[mi][ni][j] = 0.f;

    int st_load = 2, st_cmp = 0;
    for (int kt = 0; kt < NK; kt++) {
        if (kt + 2 < NK) {
            uint32_t s0 = sb + st_load * ST1;
            size_t ko = (size_t)(kt + 2) << 7;
            #pragma unroll
            for (int i = 0; i < 4; i++) {
                cp16(s0 +     0 + swo[i], (const char*)A + ga[i] + ko);
                cp16(s0 + 16384 + swo[i], (const char*)B + gb[i] + ko);
            }
            CP_COMMIT();
            if (++st_load == 3) st_load = 0;
        }
        int ahead = NK - 1 - kt; if (ahead > 2) ahead = 2;
        if (ahead == 2)      asm volatile("cp.async.wait_group 2;" ::: "memory");
        else if (ahead == 1) asm volatile("cp.async.wait_group 1;" ::: "memory");
        else                 asm volatile("cp.async.wait_group 0;" ::: "memory");
        __syncthreads();

        const uint32_t sa = sb + st_cmp * ST1;
        #pragma unroll
        for (int ks = 0; ks < 4; ks++) {
            uint32_t ah[4][4];
            const int chA = (ks << 1) + (lane >> 4);
            #pragma unroll
            for (int mi = 0; mi < 4; mi++) {
                int r = wm * 64 + mi * 16 + (lane & 15);
                uint32_t ad = sa + (uint32_t)(r * 128 + ((chA ^ (r & 7)) << 4));
                LDSM4(ah[mi], ad);
            }
            uint32_t bh[4][2];
            #pragma unroll
            for (int nb = 0; nb < 2; nb++) {
                int r = wn * 32 + nb * 16 + (lane & 15);
                uint32_t bd = sa + 16384u + (uint32_t)(r * 128 + ((chA ^ (r & 7)) << 4));
                uint32_t d[4];
                LDSM4(d, bd);
                bh[2*nb][0] = d[0];   bh[2*nb][1] = d[2];
                bh[2*nb+1][0] = d[1]; bh[2*nb+1][1] = d[3];
            }
            #pragma unroll
            for (int mi = 0; mi < 4; mi++)
                #pragma unroll
                for (int ni = 0; ni < 4; ni++)
                    MMA16816F(acc[mi][ni], ah[mi], bh[ni]);
        }
        __syncthreads();
        if (++st_cmp == 3) st_cmp = 0;
    }

    #pragma unroll
    for (int mi = 0; mi < 4; mi++) {
        int r0 = brow + wm * 64 + mi * 16 + (lane >> 2);
        #pragma unroll
        for (int ni = 0; ni < 4; ni++) {
            int c0 = bcol + wn * 32 + ni * 8 + ((lane & 3) << 1);
            *(float2*)&C[(size_t)r0 * N + c0] =
                make_float2(acc[mi][ni][0], acc[mi][ni][1]);
            *(float2*)&C[(size_t)(r0 + 8) * N + c0] =
                make_float2(acc[mi][ni][2], acc[mi][ni][3]);
        }
    }
}

// ---------------------------------------------------------------------------
// Fused causal depthwise conv (K=4) + SiLU for q/k/v in one launch.
// grid (4096, 24): y<16 -> q head (l2+scale), y<20 -> k head (l2), else v.
// ---------------------------------------------------------------------------
__global__ __launch_bounds__(128) void conv_fused(
    const float* __restrict__ xcat,
    const float* __restrict__ wq, const float* __restrict__ wk,
    const float* __restrict__ wv)
{
    const int row = blockIdx.x;
    const int y   = blockIdx.y;
    const int l   = row & (SEQ - 1);

    const float* in; const float* w; float* out;
    int c, chans, do_l2; float scale;
    if (y < 16)      { c = y * DHEAD + threadIdx.x;        in = xcat;         w = wq; out = g_q; chans = 2048; do_l2 = 1; scale = 0.08838834764831845f; }
    else if (y < 20) { c = (y - 16) * DHEAD + threadIdx.x; in = xcat + COL_K; w = wk; out = g_k; chans = 512;  do_l2 = 1; scale = 1.f; }
    else             { c = (y - 20) * DHEAD + threadIdx.x; in = xcat + COL_V; w = wv; out = g_v; chans = 512;  do_l2 = 0; scale = 1.f; }

    float acc = 0.f;
    #pragma unroll
    for (int j = 0; j < 4; j++) {
        int sl = l + j - 3;
        if (sl >= 0) acc += in[(size_t)(row + j - 3) * NCAT + c] * w[c * 4 + j];
    }
    float yv = acc / (1.f + expf(-acc));

    if (do_l2) {
        __shared__ float smr[4];
        float ss = yv * yv;
        #pragma unroll
        for (int off = 16; off > 0; off >>= 1)
            ss += __shfl_xor_sync(0xffffffffu, ss, off);
        if ((threadIdx.x & 31) == 0) smr[threadIdx.x >> 5] = ss;
        __syncthreads();
        float tot = smr[0] + smr[1] + smr[2] + smr[3];
        yv *= rsqrtf(tot + 1e-6f) * scale;
    }
    out[(size_t)row * chans + c] = yv;
}

// ---------------------------------------------------------------------------
// Gated delta-rule recurrence v3: 128 CTAs x 256 threads (2 warps/SMSP).
// CTA = (b, h, column-half). Thread t: col = t>>2, key-quarter kq = t&3
// (keys [kq*32, kq*32+32)). k-fragments cached in regs across both loops.
// Smem chunks padded to 36 floats (144B) -> conflict-free 16B loads.
// Reductions over 4 key-quarters via shfl_xor(1), shfl_xor(2).
// ---------------------------------------------------------------------------
#define FMA2(d, a, b, c) \
    asm("fma.rn.f32x2 %0, %1, %2, %3;" : "=l"(d) : "l"(a), "l"(b), "l"(c))
#define MUL2(d, a, b) \
    asm("mul.rn.f32x2 %0, %1, %2;" : "=l"(d) : "l"(a), "l"(b))

__device__ __forceinline__ unsigned long long f2pack(float a, float b) {
    unsigned long long r;
    asm("mov.b64 %0, {%1, %2};" : "=l"(r)
        : "r"(__float_as_uint(a)), "r"(__float_as_uint(b)));
    return r;
}
__device__ __forceinline__ float f2sum(unsigned long long v) {
    uint32_t x, y;
    asm("mov.b64 {%0, %1}, %2;" : "=r"(x), "=r"(y) : "l"(v));
    return __uint_as_float(x) + __uint_as_float(y);
}

__global__ __launch_bounds__(256) void recurrence_kernel()
{
    // 4 chunks of 32 floats, padded to 36-float stride (144B, 16B aligned)
    __shared__ __align__(16) float ks[2][160];
    __shared__ __align__(16) float qs[2][160];

    const int bx   = blockIdx.x;        // 0..127
    const int pair = bx >> 1;
    const int half = bx & 1;
    const int b  = pair >> 4;
    const int h  = pair & 15;
    const int kh = h >> 2;
    const int t  = threadIdx.x;
    const int col  = t >> 2;            // 0..63 local column
    const int gcol = half * 64 + col;
    const int kq   = t & 3;             // key-quarter

    unsigned long long S2[16];          // 32 keys x 1 col
    #pragma unroll
    for (int d = 0; d < 16; d++) S2[d] = 0ull;

    const float* kp = g_k    + ((size_t)(b * SEQ) * NHK + kh) * DHEAD;
    const float* qp = g_q    + ((size_t)(b * SEQ) * NH  + h ) * DHEAD;
    const float* vp = g_v    + ((size_t)(b * SEQ) * NHK + kh) * DHEAD + gcol;
    const float* gp = g_gd   +  (size_t)(b * SEQ) * NH + h;
    const float* bp = g_beta +  (size_t)(b * SEQ) * NH + h;
    float*       op = g_o    + ((size_t)(b * SEQ) * NH  + h ) * DHEAD + gcol;

    // loader role: t<128 loads k[key=t], t>=128 loads q[key=t-128]
    const int key  = t & 127;
    const int spos = ((key >> 5) * 36) + (key & 31);
    const bool isK = (t < 128);
    const float*  lp      = isK ? (kp + key) : (qp + key);
    const size_t  lstride = isK ? 512 : 2048;

    float lcur = lp[0];
    float vcur = vp[0], gcur = gp[0], bcur = bp[0];
    if (isK) ks[0][spos] = lcur; else qs[0][spos] = lcur;
    __syncthreads();

    for (int l = 0; l < SEQ; l++) {
        const int cur = l & 1, nxt = cur ^ 1;
        float lnx = 0.f, vnx = 0.f, gnx = 0.f, bnx = 0.f;
        if (l + 1 < SEQ) {
            lnx = lp[(size_t)(l + 1) * lstride];
            vnx = vp[(size_t)(l + 1) * 512];
            gnx = gp[(size_t)(l + 1) * NH];
            bnx = bp[(size_t)(l + 1) * NH];
        }

        const float eg = expf(gcur);
        const unsigned long long eg2 = f2pack(eg, eg);
        const ulonglong2* k2p = reinterpret_cast<const ulonglong2*>(&ks[cur][kq * 36]);
        const ulonglong2* q2p = reinterpret_cast<const ulonglong2*>(&qs[cur][kq * 36]);

        ulonglong2 kk[8];
        unsigned long long kva = 0ull, kvb = 0ull;
        #pragma unroll
        for (int i = 0; i < 8; i++) {
            kk[i] = k2p[i];
            MUL2(S2[2 * i], S2[2 * i], eg2);
            FMA2(kva, kk[i].x, S2[2 * i], kva);
            MUL2(S2[2 * i + 1], S2[2 * i + 1], eg2);
            FMA2(kvb, kk[i].y, S2[2 * i + 1], kvb);
        }
        float kvp = f2sum(kva) + f2sum(kvb);
        kvp += __shfl_xor_sync(0xffffffffu, kvp, 1);
        kvp += __shfl_xor_sync(0xffffffffu, kvp, 2);
        const float cc = bcur * (vcur - kvp);
        const unsigned long long cc2 = f2pack(cc, cc);

        unsigned long long qa = 0ull, qb = 0ull;
        #pragma unroll
        for (int i = 0; i < 8; i++) {
            ulonglong2 qq = q2p[i];
            FMA2(S2[2 * i], kk[i].x, cc2, S2[2 * i]);
            FMA2(qa, qq.x, S2[2 * i], qa);
            FMA2(S2[2 * i + 1], kk[i].y, cc2, S2[2 * i + 1]);
            FMA2(qb, qq.y, S2[2 * i + 1], qb);
        }
        float qo = f2sum(qa) + f2sum(qb);
        qo += __shfl_xor_sync(0xffffffffu, qo, 1);
        qo += __shfl_xor_sync(0xffffffffu, qo, 2);
        if (kq == 0) op[(size_t)l * 2048] = qo;

        if (isK) ks[nxt][spos] = lnx; else qs[nxt][spos] = lnx;
        __syncthreads();
        vcur = vnx; gcur = gnx; bcur = bnx;
    }
}

// ---------------------------------------------------------------------------
// FusedRMSNormGated -> fp16 (single rounding; gate from xcat col 3072+)
// ---------------------------------------------------------------------------
__global__ __launch_bounds__(128) void rmsgate_kernel(
    const float* __restrict__ xcat, const float* __restrict__ w)
{
    const int row = blockIdx.x;
    const int h   = blockIdx.y;
    const int t   = threadIdx.x;

    const size_t idx = (size_t)(row * NH + h) * DHEAD + t;
    float o = g_o[idx];

    float ss = o * o;
    #pragma unroll
    for (int off = 16; off > 0; off >>= 1)
        ss += __shfl_xor_sync(0xffffffffu, ss, off);
    __shared__ float sm[4];
    if ((t & 31) == 0) sm[t >> 5] = ss;
    __syncthreads();
    float tot = sm[0] + sm[1] + sm[2] + sm[3];
    float r = rsqrtf(tot * (1.f / 128.f) + 1e-5f);

    float gate = xcat[(size_t)row * NCAT + COL_G + h * DHEAD + t];
    float sg   = gate / (1.f + expf(-gate));
    float val  = o * r * w[t] * sg;
    g_of[(size_t)row * DH_ + h * DHEAD + t] = __float2half_rn(val);
}

// ---------------------------------------------------------------------------
// Launch: fused_prep(1), gemm1(2), conv_fused(3), recurrence(4 <- ncu),
//         rmsgate(5), gemm1-out(6)
// ---------------------------------------------------------------------------
extern "C" void kernel_launch(void* const* d_in, const int* in_sizes, int n_in,
                              void* d_out, int out_size)
{
    (void)in_sizes; (void)n_in; (void)out_size;
    const float* x     = (const float*)d_in[0];
    const float* Wq    = (const float*)d_in[1];
    const float* Wk    = (const float*)d_in[2];
    const float* Wv    = (const float*)d_in[3];
    const float* Wb    = (const float*)d_in[4];
    const float* Wgk   = (const float*)d_in[5];
    const float* A_log = (const float*)d_in[6];
    const float* dt_b  = (const float*)d_in[7];
    const float* convq = (const float*)d_in[8];
    const float* convk = (const float*)d_in[9];
    const float* convv = (const float*)d_in[10];
    const float* Wg    = (const float*)d_in[11];
    const float* onw   = (const float*)d_in[12];
    const float* Wo    = (const float*)d_in[13];
    float* out = (float*)d_out;

    cudaFuncSetAttribute(gemm1, cudaFuncAttributeMaxDynamicSharedMemorySize, SM1);
    cudaFuncSetAttribute(fused_prep, cudaFuncAttributeMaxDynamicSharedMemorySize, 65536);

    float *p_xcat;
    __half *p_xhi, *p_of, *p_wcat, *p_wot;
    cudaGetSymbolAddress((void**)&p_xcat, g_xcat);
    cudaGetSymbolAddress((void**)&p_xhi, g_xhi);
    cudaGetSymbolAddress((void**)&p_of,  g_of);
    cudaGetSymbolAddress((void**)&p_wcat, g_wcat);
    cudaGetSymbolAddress((void**)&p_wot,  g_wot);

    // 1) tof16 + transposes + betag
    fused_prep<<<PREP_NB, 256, 65536>>>(x, Wq, Wk, Wv, Wg, Wo, Wb, Wgk,
                                        A_log, dt_b, p_xhi, p_wcat, p_wot);
    // 2) fused projection GEMM
    gemm1<<<dim3(NCAT / 128, 32), 256, SM1>>>(p_xhi, p_wcat, p_xcat, NCAT, DH_);
    // 3) all convs
    conv_fused<<<dim3(ROWS, 24), 128>>>(p_xcat, convq, convk, convv);
    // 4) recurrence   <-- ncu capture target
    recurrence_kernel<<<128, 256>>>();
    // 5) gated rmsnorm (-> fp16)
    rmsgate_kernel<<<dim3(ROWS, 16), 128>>>(p_xcat, onw);
    // 6) output projection
    gemm1<<<dim3(16, 32), 256, SM1>>>(p_of, p_wot, out, 2048, DH_);
}